// round 2
// baseline (speedup 1.0000x reference)
#include <cuda_runtime.h>

// ---------------------------------------------------------------------------
// HierarchicalBlockShuffleLayer: LN -> {flip(blockdiag 16x16), alpha * Monarch} + bias
// D = 1024, BLOCK = 16 (G=64), sq = 32.
//
// Precompute (prep kernel):
//   g_M[c][s]  = alpha * sum_k W_col[c,k] * W_row[s,k]          (32x32)
//   g_Wf[h][b][j] = BW[63-h][b][15-j]                            (64x16x16)
// Then per row:
//   out[32r + s]    = sum_c xn[32r+c] * M[c][s]   (Monarch, alpha folded)
//                   + blockdiag via Wf (uses xn chunk 31-r)
//                   + bias[32r+s]
// ---------------------------------------------------------------------------

#define THREADS 512
#define ROWS_PER_TILE 32

__device__ float g_M[32 * 32];       // alpha-scaled monarch matrix
__device__ float g_Wf[64 * 16 * 16]; // flip-folded block weights

typedef unsigned long long u64;

__device__ __forceinline__ u64 pack2(float a, float b) {
    u64 r; asm("mov.b64 %0, {%1, %2};" : "=l"(r) : "f"(a), "f"(b)); return r;
}
__device__ __forceinline__ u64 dup2(float a) { return pack2(a, a); }
__device__ __forceinline__ u64 fma2(u64 a, u64 b, u64 c) {
    u64 d; asm("fma.rn.f32x2 %0, %1, %2, %3;" : "=l"(d) : "l"(a), "l"(b), "l"(c)); return d;
}

// ---------------------------------------------------------------------------
// Prep kernel: tiny, runs once per launch (deterministic).
// ---------------------------------------------------------------------------
__global__ void prep_kernel(const float* __restrict__ bw,
                            const float* __restrict__ wrow,
                            const float* __restrict__ wcol,
                            const float* __restrict__ alpha_p) {
    int t = blockIdx.x * blockDim.x + threadIdx.x;
    float alpha = alpha_p[0];
    if (t < 1024) {
        int c = t >> 5, s = t & 31;
        float acc = 0.f;
#pragma unroll
        for (int k = 0; k < 32; k++) acc += wcol[c * 32 + k] * wrow[s * 32 + k];
        g_M[t] = alpha * acc;
    }
    for (int i = t; i < 16384; i += blockDim.x * gridDim.x) {
        int h = i >> 8, b = (i >> 4) & 15, j = i & 15;
        g_Wf[i] = bw[(63 - h) * 256 + b * 16 + (15 - j)];
    }
}

// ---------------------------------------------------------------------------
// Shared memory layout (floats):
//   XNT   [1024][33]  transposed, padded normalized tile   (33792)
//   WF    16384
//   M     1024
//   BIAS  1024
//   GA    1024
//   BE    1024
//   MU    32
//   RS    32
// Total = 54336 floats = 217344 bytes
// ---------------------------------------------------------------------------
#define OFF_XNT  0
#define OFF_WF   33792
#define OFF_M    50176
#define OFF_BIAS 51200
#define OFF_GA   52224
#define OFF_BE   53248
#define OFF_MU   54272
#define OFF_RS   54304
#define SMEM_FLOATS 54336
#define SMEM_BYTES (SMEM_FLOATS * 4)

__global__ void __launch_bounds__(THREADS, 1)
hbsl_kernel(const float* __restrict__ x,
            const float* __restrict__ gamma,
            const float* __restrict__ beta,
            const float* __restrict__ bias,
            float* __restrict__ out,
            int ntiles) {
    extern __shared__ float sm[];
    float* XNT  = sm + OFF_XNT;
    float* WF   = sm + OFF_WF;
    float* M    = sm + OFF_M;
    float* BIAS = sm + OFF_BIAS;
    float* GA   = sm + OFF_GA;
    float* BE   = sm + OFF_BE;
    float* MU   = sm + OFF_MU;
    float* RS   = sm + OFF_RS;

    const int t = threadIdx.x;
    const int w = t >> 5;   // warp id 0..15
    const int l = t & 31;   // lane

    // Per-block one-time weight staging (L2-hot after first block)
    for (int i = t; i < 16384; i += THREADS) WF[i] = g_Wf[i];
    for (int i = t; i < 1024; i += THREADS) {
        M[i] = g_M[i]; BIAS[i] = bias[i]; GA[i] = gamma[i]; BE[i] = beta[i];
    }
    __syncthreads();

    const u64* __restrict__ M2  = (const u64*)M;
    const u64* __restrict__ WF2 = (const u64*)WF;
    const u64* __restrict__ B2  = (const u64*)BIAS;

    for (int tile = blockIdx.x; tile < ntiles; tile += gridDim.x) {
        const long base = (long)tile * ROWS_PER_TILE * 1024;

        // ---- Load + transpose + stats: warp w handles tile rows 2w, 2w+1 ----
#pragma unroll
        for (int rr = 0; rr < 2; rr++) {
            const int row = 2 * w + rr;
            const float* __restrict__ xr = x + base + (long)row * 1024;
            float sum = 0.f, sq = 0.f;
#pragma unroll
            for (int q = 0; q < 8; q++) {
#pragma unroll
                for (int e = 0; e < 4; e++) {
                    const int idx = q * 128 + e * 32 + l;   // lanes consecutive -> coalesced
                    const float v = xr[idx];
                    XNT[idx * 33 + row] = v;                // conflict-free (bank = (idx+row)%32 -> distinct per lane)
                    sum += v; sq += v * v;
                }
            }
#pragma unroll
            for (int o = 16; o > 0; o >>= 1) {
                sum += __shfl_xor_sync(0xffffffffu, sum, o);
                sq  += __shfl_xor_sync(0xffffffffu, sq,  o);
            }
            if (l == 0) {
                const float mu = sum * (1.f / 1024.f);
                const float var = sq * (1.f / 1024.f) - mu * mu;
                MU[row] = mu;
                RS[row] = rsqrtf(var + 1e-5f);
            }
        }
        __syncthreads();

        // ---- Normalize in place: thread t handles d = 2t, 2t+1 over all 32 rows ----
#pragma unroll
        for (int dd = 0; dd < 2; dd++) {
            const int d = 2 * t + dd;
            const float g = GA[d], b = BE[d];
            float* p = XNT + d * 33;
#pragma unroll
            for (int i = 0; i < 32; i++) {
                p[i] = (p[i] - MU[i]) * RS[i] * g + b;
            }
        }
        __syncthreads();

        // ---- Compute: warp w -> output chunk pair (w, 31-w); lane l -> row l ----
        {
            const int r = w;
            const int q = 31 - w;
            u64 accr[16], accq[16];
#pragma unroll
            for (int s2 = 0; s2 < 16; s2++) {
                accr[s2] = B2[r * 16 + s2];
                accq[s2] = B2[q * 16 + s2];
            }

            // Monarch: both chunks share M[c][*] loads (broadcast LDS.64)
            const float* __restrict__ xnr = XNT + (r * 32) * 33 + l;
            const float* __restrict__ xnq = XNT + (q * 32) * 33 + l;
#pragma unroll 4
            for (int c = 0; c < 32; c++) {
                const u64 xa = dup2(xnr[c * 33]);
                const u64 xb = dup2(xnq[c * 33]);
                const u64* __restrict__ mrow = M2 + c * 16;
#pragma unroll
                for (int s2 = 0; s2 < 16; s2++) {
                    const u64 m = mrow[s2];
                    accr[s2] = fma2(xa, m, accr[s2]);
                    accq[s2] = fma2(xb, m, accq[s2]);
                }
            }

            // Block-diagonal (flip folded into WF):
            //   out chunk r, s in [0,16):   group 63-2w (d base 1008-32w), Wf[2w]
            //   out chunk r, s in [16,32):  group 62-2w (d base  992-32w), Wf[2w+1]
            //   out chunk q, s in [0,16):   group 2w+1  (d base 32w+16),   Wf[62-2w]
            //   out chunk q, s in [16,32):  group 2w    (d base 32w),      Wf[63-2w]
            const float* __restrict__ gp0 = XNT + (1008 - 32 * w) * 33 + l;
            const float* __restrict__ gp1 = XNT + (992 - 32 * w) * 33 + l;
            const float* __restrict__ gp2 = XNT + (32 * w + 16) * 33 + l;
            const float* __restrict__ gp3 = XNT + (32 * w) * 33 + l;
            const u64* __restrict__ W0 = WF2 + (2 * w) * 128;
            const u64* __restrict__ W1 = WF2 + (2 * w + 1) * 128;
            const u64* __restrict__ W2 = WF2 + (62 - 2 * w) * 128;
            const u64* __restrict__ W3 = WF2 + (63 - 2 * w) * 128;
#pragma unroll 2
            for (int b = 0; b < 16; b++) {
                const u64 v0 = dup2(gp0[b * 33]);
                const u64 v1 = dup2(gp1[b * 33]);
                const u64 v2 = dup2(gp2[b * 33]);
                const u64 v3 = dup2(gp3[b * 33]);
#pragma unroll
                for (int j2 = 0; j2 < 8; j2++) {
                    accr[j2]     = fma2(v0, W0[b * 8 + j2], accr[j2]);
                    accr[8 + j2] = fma2(v1, W1[b * 8 + j2], accr[8 + j2]);
                    accq[j2]     = fma2(v2, W2[b * 8 + j2], accq[j2]);
                    accq[8 + j2] = fma2(v3, W3[b * 8 + j2], accq[8 + j2]);
                }
            }

            // Store: lane l owns row (tile*32 + l); 8x STG.128 per chunk
            float* __restrict__ orow = out + base + (long)l * 1024;
            float4* __restrict__ pr = (float4*)(orow + 32 * r);
            float4* __restrict__ pq = (float4*)(orow + 32 * q);
#pragma unroll
            for (int k = 0; k < 8; k++) {
                const float2 a0 = *(const float2*)&accr[2 * k];
                const float2 a1 = *(const float2*)&accr[2 * k + 1];
                pr[k] = make_float4(a0.x, a0.y, a1.x, a1.y);
            }
#pragma unroll
            for (int k = 0; k < 8; k++) {
                const float2 a0 = *(const float2*)&accq[2 * k];
                const float2 a1 = *(const float2*)&accq[2 * k + 1];
                pq[k] = make_float4(a0.x, a0.y, a1.x, a1.y);
            }
        }
        __syncthreads();  // protect XNT before next tile
    }
}

// ---------------------------------------------------------------------------
extern "C" void kernel_launch(void* const* d_in, const int* in_sizes, int n_in,
                              void* d_out, int out_size) {
    const float* x     = (const float*)d_in[0];
    const float* gamma = (const float*)d_in[1];
    const float* beta  = (const float*)d_in[2];
    const float* bw    = (const float*)d_in[3];
    const float* wrow  = (const float*)d_in[4];
    const float* wcol  = (const float*)d_in[5];
    const float* alpha = (const float*)d_in[6];
    const float* bias  = (const float*)d_in[7];
    float* out = (float*)d_out;

    const int rows = in_sizes[0] / 1024;
    const int ntiles = rows / ROWS_PER_TILE;

    prep_kernel<<<16, 1024>>>(bw, wrow, wcol, alpha);

    cudaFuncSetAttribute(hbsl_kernel,
                         cudaFuncAttributeMaxDynamicSharedMemorySize, SMEM_BYTES);
    hbsl_kernel<<<148, THREADS, SMEM_BYTES>>>(x, gamma, beta, bias, out, ntiles);
}

// round 3
// speedup vs baseline: 1.0621x; 1.0621x over previous
#include <cuda_runtime.h>

// ---------------------------------------------------------------------------
// HierarchicalBlockShuffleLayer, fully folded:
//   xn = rs*(v*gamma) - mu*rs*gamma + beta
//   out[32r+s] = rs*A + (mu*rs)*C2[r,s] + C1[r,s]
//   A = sum_c vg[32r+c]*M[c][s]  +  sum_b vg[32(31-r)+off(s)+b]*T[r][b][s]
//   M = alpha * Wcol @ Wrow^T ; T = flip-rearranged block_weights
//   C2 = -(gamma-weighted col sums), C1 = beta-weighted col sums + bias
// f32x2 packs ROW PAIRS; weights amortized over 4 rows per LDS.
// ---------------------------------------------------------------------------

typedef unsigned long long u64;

#define THREADS 512
#define ROWS_PER_TILE 32
#define XSTRIDE 36          // floats per dim-row in smem tile (16B-align + low conflict)

__device__ u64   g_MD[1024];     // M[c][s] duplicated {m,m}
__device__ float g_T [16384];    // T[r][b][s]
__device__ float g_C1[1024];     // [r][s]
__device__ float g_C2[1024];     // [r][s]

__device__ __forceinline__ u64 pack2(float a, float b) {
    u64 r; asm("mov.b64 %0, {%1, %2};" : "=l"(r) : "f"(a), "f"(b)); return r;
}
__device__ __forceinline__ u64 dup2(float a) { return pack2(a, a); }
__device__ __forceinline__ void unpack2(float& a, float& b, u64 v) {
    asm("mov.b64 {%0, %1}, %2;" : "=f"(a), "=f"(b) : "l"(v));
}
__device__ __forceinline__ u64 fma2(u64 a, u64 b, u64 c) {
    u64 d; asm("fma.rn.f32x2 %0, %1, %2, %3;" : "=l"(d) : "l"(a), "l"(b), "l"(c)); return d;
}
__device__ __forceinline__ u64 add2(u64 a, u64 b) {
    u64 d; asm("add.rn.f32x2 %0, %1, %2;" : "=l"(d) : "l"(a), "l"(b)); return d;
}
__device__ __forceinline__ u64 mul2(u64 a, u64 b) {
    u64 d; asm("mul.rn.f32x2 %0, %1, %2;" : "=l"(d) : "l"(a), "l"(b)); return d;
}

// ---------------------------------------------------------------------------
// Prep: build M (alpha folded), T (flip folded), C1/C2 (LN affine folded).
// Single block of 1024 threads; thread t = (hi, s) with hi = c then r.
// ---------------------------------------------------------------------------
__global__ void prep_kernel(const float* __restrict__ bw,
                            const float* __restrict__ wrow,
                            const float* __restrict__ wcol,
                            const float* __restrict__ alpha_p,
                            const float* __restrict__ gamma,
                            const float* __restrict__ beta,
                            const float* __restrict__ bias) {
    __shared__ float Msm[1024];
    const int t  = threadIdx.x;
    const int hi = t >> 5, s = t & 31;
    const float alpha = alpha_p[0];
    {
        const int c = hi;
        float acc = 0.f;
#pragma unroll
        for (int k = 0; k < 32; k++) acc += wcol[c * 32 + k] * wrow[s * 32 + k];
        const float m = alpha * acc;
        Msm[c * 32 + s] = m;
        g_MD[c * 32 + s] = pack2(m, m);
    }
    __syncthreads();
    const int r = hi;
    float Gm = 0.f, Bm = 0.f;
#pragma unroll
    for (int c = 0; c < 32; c++) {
        const float m = Msm[c * 32 + s];
        Gm += gamma[32 * r + c] * m;
        Bm += beta [32 * r + c] * m;
    }
    const int o   = (s < 16) ? 16 : 0;
    const int j   = (s < 16) ? (15 - s) : (31 - s);
    const int grp = (s < 16) ? (63 - 2 * r) : (62 - 2 * r);
    float Gb = 0.f, Bb = 0.f;
#pragma unroll
    for (int b = 0; b < 16; b++) {
        const float wv = bw[grp * 256 + b * 16 + j];
        g_T[r * 512 + b * 32 + s] = wv;
        Gb += gamma[32 * (31 - r) + o + b] * wv;
        Bb += beta [32 * (31 - r) + o + b] * wv;
    }
    g_C1[t] = Bm + Bb + bias[32 * r + s];
    g_C2[t] = -(Gm + Gb);
}

// ---------------------------------------------------------------------------
// SMEM: XP [1024][36] floats (147456B) | TS 65536B | MD 8192B | RSPK/MURSPK
// ---------------------------------------------------------------------------
#define OFF_TS   147456
#define OFF_MD   212992
#define OFF_RS   221184
#define OFF_MURS 221312
#define SMEM_BYTES 221440

__global__ void __launch_bounds__(THREADS, 1)
hbsl_kernel(const float* __restrict__ x,
            const float* __restrict__ gamma,
            float* __restrict__ out,
            int ntiles) {
    extern __shared__ unsigned char smraw[];
    float* XP     = (float*)smraw;                 // transposed vg tile
    float* TS     = (float*)(smraw + OFF_TS);      // T[r][b][s]
    u64*   MD     = (u64*)  (smraw + OFF_MD);      // M dup'd [c][s]
    u64*   RSPK   = (u64*)  (smraw + OFF_RS);      // {rs_even, rs_odd} per row pair
    u64*   MURSPK = (u64*)  (smraw + OFF_MURS);

    const int t = threadIdx.x;
    const int w = t >> 5, l = t & 31;

    for (int i = t; i < 16384; i += THREADS) TS[i] = g_T[i];
    for (int i = t; i < 1024;  i += THREADS) MD[i] = g_MD[i];

    // per-warp constants (fixed across tiles)
    const int r = w, q = 31 - w;
    const u64 C1r = dup2(g_C1[r * 32 + l]);
    const u64 C2r = dup2(g_C2[r * 32 + l]);
    const u64 C1q = dup2(g_C1[q * 32 + l]);
    const u64 C2q = dup2(g_C2[q * 32 + l]);
    const int off = (l < 16) ? 16 : 0;
    const float* xMr = XP + (32 * r) * XSTRIDE;        // monarch x, chunk r
    const float* xMq = XP + (32 * q) * XSTRIDE;        // monarch x, chunk q
    const float* xBr = XP + (32 * q + off) * XSTRIDE;  // block x for chunk-r outputs
    const float* xBq = XP + (32 * r + off) * XSTRIDE;  // block x for chunk-q outputs
    const float* Trp = TS + r * 512 + l;
    const float* Tqp = TS + q * 512 + l;
    __syncthreads();

    for (int tile = blockIdx.x; tile < ntiles; tile += gridDim.x) {
        const size_t base = (size_t)tile * ROWS_PER_TILE * 1024;

        // ---- load rows 2w,2w+1: stats on v, store vg = v*gamma transposed ----
        {
            const float* x0 = x + base + (size_t)(2 * w) * 1024;
            const float* x1 = x0 + 1024;
            u64 s2 = 0ull, q2 = 0ull;
#pragma unroll 8
            for (int k = 0; k < 32; k++) {
                const int d = k * 32 + l;                 // coalesced
                const u64 v2 = pack2(x0[d], x1[d]);
                s2 = add2(s2, v2);
                q2 = fma2(v2, v2, q2);
                const u64 vg = mul2(v2, dup2(gamma[d]));
                *(u64*)(XP + d * XSTRIDE + 2 * w) = vg;   // 8B aligned, ~2-way conflict
            }
            float s0, s1, qq0, qq1;
            unpack2(s0, s1, s2); unpack2(qq0, qq1, q2);
#pragma unroll
            for (int o2 = 16; o2 > 0; o2 >>= 1) {
                s0  += __shfl_xor_sync(~0u, s0,  o2);
                s1  += __shfl_xor_sync(~0u, s1,  o2);
                qq0 += __shfl_xor_sync(~0u, qq0, o2);
                qq1 += __shfl_xor_sync(~0u, qq1, o2);
            }
            if (l == 0) {
                const float mu0 = s0 * (1.f / 1024.f), mu1 = s1 * (1.f / 1024.f);
                const float rs0 = rsqrtf(qq0 * (1.f / 1024.f) - mu0 * mu0 + 1e-5f);
                const float rs1 = rsqrtf(qq1 * (1.f / 1024.f) - mu1 * mu1 + 1e-5f);
                RSPK[w]   = pack2(rs0, rs1);
                MURSPK[w] = pack2(mu0 * rs0, mu1 * rs1);
            }
        }
        __syncthreads();

        // ---- compute: 8 groups of 4 rows; lane = s; warp = chunk pair (r, q) ----
#pragma unroll 1
        for (int g4 = 0; g4 < 8; g4++) {
            const int go = 4 * g4;
            u64 ar0 = 0, ar1 = 0, aq0 = 0, aq1 = 0;
            const float* pMr = xMr + go;
            const float* pMq = xMq + go;
#pragma unroll
            for (int c = 0; c < 32; c++) {
                const ulonglong2 xr = *(const ulonglong2*)(pMr + c * XSTRIDE); // 4 rows, broadcast
                const ulonglong2 xq = *(const ulonglong2*)(pMq + c * XSTRIDE);
                const u64 m = MD[c * 32 + l];
                ar0 = fma2(xr.x, m, ar0); ar1 = fma2(xr.y, m, ar1);
                aq0 = fma2(xq.x, m, aq0); aq1 = fma2(xq.y, m, aq1);
            }
            const float* pBr = xBr + go;
            const float* pBq = xBq + go;
#pragma unroll
            for (int b = 0; b < 16; b++) {
                const ulonglong2 x1v = *(const ulonglong2*)(pBr + b * XSTRIDE); // lane-split 2 addrs
                const ulonglong2 x2v = *(const ulonglong2*)(pBq + b * XSTRIDE);
                const u64 wr = dup2(Trp[b * 32]);
                const u64 wq = dup2(Tqp[b * 32]);
                ar0 = fma2(x1v.x, wr, ar0); ar1 = fma2(x1v.y, wr, ar1);
                aq0 = fma2(x2v.x, wq, aq0); aq1 = fma2(x2v.y, wq, aq1);
            }
            // epilogue: out = rs*A + murs*C2 + C1 ; rows packed {even, odd}
            float* orow = out + base + (size_t)go * 1024;
#pragma unroll
            for (int rp = 0; rp < 2; rp++) {
                const u64 RS2 = RSPK[2 * g4 + rp];
                const u64 MU2 = MURSPK[2 * g4 + rp];
                const u64 vr = fma2(RS2, rp ? ar1 : ar0, fma2(MU2, C2r, C1r));
                const u64 vq = fma2(RS2, rp ? aq1 : aq0, fma2(MU2, C2q, C1q));
                float a, bv;
                unpack2(a, bv, vr);
                orow[(2 * rp)     * 1024 + 32 * r + l] = a;   // coalesced 128B
                orow[(2 * rp + 1) * 1024 + 32 * r + l] = bv;
                unpack2(a, bv, vq);
                orow[(2 * rp)     * 1024 + 32 * q + l] = a;
                orow[(2 * rp + 1) * 1024 + 32 * q + l] = bv;
            }
        }
        __syncthreads();
    }
}

// ---------------------------------------------------------------------------
extern "C" void kernel_launch(void* const* d_in, const int* in_sizes, int n_in,
                              void* d_out, int out_size) {
    const float* x     = (const float*)d_in[0];
    const float* gamma = (const float*)d_in[1];
    const float* beta  = (const float*)d_in[2];
    const float* bw    = (const float*)d_in[3];
    const float* wrow  = (const float*)d_in[4];
    const float* wcol  = (const float*)d_in[5];
    const float* alpha = (const float*)d_in[6];
    const float* bias  = (const float*)d_in[7];
    float* out = (float*)d_out;

    const int rows = in_sizes[0] / 1024;
    const int ntiles = rows / ROWS_PER_TILE;

    prep_kernel<<<1, 1024>>>(bw, wrow, wcol, alpha, gamma, beta, bias);

    cudaFuncSetAttribute(hbsl_kernel,
                         cudaFuncAttributeMaxDynamicSharedMemorySize, SMEM_BYTES);
    hbsl_kernel<<<148, THREADS, SMEM_BYTES>>>(x, gamma, out, ntiles);
}

// round 4
// speedup vs baseline: 1.1665x; 1.0982x over previous
#include <cuda_runtime.h>

// ---------------------------------------------------------------------------
// HierarchicalBlockShuffleLayer, fully folded, register-resident weights:
//   out[32r+s] = rs*A + (mu*rs)*C2[r,s] + C1[r,s]
//   A = sum_c vg[32r+c]*M[c][s] + sum_b vg[32(31-r)+off(s)+b]*T[r][b][s]
//   vg = x * gamma;  M = alpha*Wcol@Wrow^T;  T = flip-folded block weights
//   C2 = -(gamma-weighted col sums), C1 = beta-weighted col sums + bias
// Lane = s. f32x2 packs row pairs. M[.][l], T[.][.][l] live in registers.
// Smem tile: dim-major, stride 36, +4 pad per odd 16-dim group (bank fix).
// ---------------------------------------------------------------------------

typedef unsigned long long u64;

#define THREADS 512
#define XSTR 36

__device__ float g_M [1024];     // M[c][s], alpha folded
__device__ float g_T [16384];    // T[r][b][s], flip folded
__device__ float g_C1[1024];     // [r][s]
__device__ float g_C2[1024];     // [r][s]

__device__ __forceinline__ u64 pack2(float a, float b) {
    u64 r; asm("mov.b64 %0, {%1, %2};" : "=l"(r) : "f"(a), "f"(b)); return r;
}
__device__ __forceinline__ u64 dup2(float a) { return pack2(a, a); }
__device__ __forceinline__ void unpack2(float& a, float& b, u64 v) {
    asm("mov.b64 {%0, %1}, %2;" : "=f"(a), "=f"(b) : "l"(v));
}
__device__ __forceinline__ u64 fma2(u64 a, u64 b, u64 c) {
    u64 d; asm("fma.rn.f32x2 %0, %1, %2, %3;" : "=l"(d) : "l"(a), "l"(b), "l"(c)); return d;
}

// ---------------------------------------------------------------------------
__global__ void prep_kernel(const float* __restrict__ bw,
                            const float* __restrict__ wrow,
                            const float* __restrict__ wcol,
                            const float* __restrict__ alpha_p,
                            const float* __restrict__ gamma,
                            const float* __restrict__ beta,
                            const float* __restrict__ bias) {
    __shared__ float Msm[1024];
    const int t  = threadIdx.x;
    const int hi = t >> 5, s = t & 31;
    const float alpha = alpha_p[0];
    {
        const int c = hi;
        float acc = 0.f;
#pragma unroll
        for (int k = 0; k < 32; k++) acc += wcol[c * 32 + k] * wrow[s * 32 + k];
        const float m = alpha * acc;
        Msm[c * 32 + s] = m;
        g_M[c * 32 + s] = m;
    }
    __syncthreads();
    const int r = hi;
    float Gm = 0.f, Bm = 0.f;
#pragma unroll
    for (int c = 0; c < 32; c++) {
        const float m = Msm[c * 32 + s];
        Gm += gamma[32 * r + c] * m;
        Bm += beta [32 * r + c] * m;
    }
    const int o   = (s < 16) ? 16 : 0;
    const int j   = (s < 16) ? (15 - s) : (31 - s);
    const int grp = (s < 16) ? (63 - 2 * r) : (62 - 2 * r);
    float Gb = 0.f, Bb = 0.f;
#pragma unroll
    for (int b = 0; b < 16; b++) {
        const float wv = bw[grp * 256 + b * 16 + j];
        g_T[r * 512 + b * 32 + s] = wv;
        Gb += gamma[32 * (31 - r) + o + b] * wv;
        Bb += beta [32 * (31 - r) + o + b] * wv;
    }
    g_C1[t] = Bm + Bb + bias[32 * r + s];
    g_C2[t] = -(Gm + Gb);
}

// ---------------------------------------------------------------------------
// Smem: XP 36864 floats (tile) | RSPK 16 u64 | MURSPK 16 u64
// ---------------------------------------------------------------------------
#define XP_FLOATS 36864
#define SMEM_BYTES (XP_FLOATS * 4 + 256)

__global__ void __launch_bounds__(THREADS, 1)
hbsl_kernel(const float* __restrict__ x,
            const float* __restrict__ gamma,
            float* __restrict__ out,
            int ntiles) {
    extern __shared__ float XP[];
    u64* RSPK   = (u64*)(XP + XP_FLOATS);
    u64* MURSPK = RSPK + 16;

    const int t = threadIdx.x;
    const int w = t >> 5, l = t & 31;
    const int r = w, q = 31 - w;

    // ---- persistent register weights / constants ----
    float Mreg[32], Tr[16], Tq[16];
#pragma unroll
    for (int c = 0; c < 32; c++) Mreg[c] = g_M[c * 32 + l];
#pragma unroll
    for (int b = 0; b < 16; b++) {
        Tr[b] = g_T[r * 512 + b * 32 + l];
        Tq[b] = g_T[q * 512 + b * 32 + l];
    }
    const u64 C1r = dup2(g_C1[r * 32 + l]), C2r = dup2(g_C2[r * 32 + l]);
    const u64 C1q = dup2(g_C1[q * 32 + l]), C2q = dup2(g_C2[q * 32 + l]);

    // pad: dim groups [16k,16k+16) with odd k get +4 floats (bank decorrelation)
    const int padl = (l & 16) >> 2;   // store-side pad for this lane's dims

    // compute-phase base pointers (dims of chunk r: first 16 no pad, last 16 +4)
    const float* mr0 = XP + (32 * r)      * XSTR;
    const float* mr1 = XP + (32 * r + 16) * XSTR + 4;
    const float* mq0 = XP + (32 * q)      * XSTR;
    const float* mq1 = XP + (32 * q + 16) * XSTR + 4;
    const float* br  = XP + ((l < 16) ? (32 * q + 16) * XSTR + 4 : (32 * q) * XSTR);
    const float* bq  = XP + ((l < 16) ? (32 * r + 16) * XSTR + 4 : (32 * r) * XSTR);

    for (int tile = blockIdx.x; tile < ntiles; tile += gridDim.x) {
        const size_t base = (size_t)tile * 32768;   // 32 rows * 1024

        // ---- load rows 2w,2w+1: stats on raw x, store vg = x*gamma transposed ----
        {
            const float* x0 = x + base + (size_t)(2 * w) * 1024;
            const float* x1 = x0 + 1024;
            float s0 = 0.f, s1 = 0.f, p0 = 0.f, p1 = 0.f;
#pragma unroll 8
            for (int k = 0; k < 32; k++) {
                const int d = k * 32 + l;                 // coalesced
                const float v0 = __ldg(x0 + d);
                const float v1 = __ldg(x1 + d);
                const float g  = __ldg(gamma + d);
                s0 += v0; s1 += v1; p0 += v0 * v0; p1 += v1 * v1;
                *(u64*)(XP + d * XSTR + padl + 2 * w) = pack2(v0 * g, v1 * g);
            }
#pragma unroll
            for (int o2 = 16; o2 > 0; o2 >>= 1) {
                s0 += __shfl_xor_sync(~0u, s0, o2);
                s1 += __shfl_xor_sync(~0u, s1, o2);
                p0 += __shfl_xor_sync(~0u, p0, o2);
                p1 += __shfl_xor_sync(~0u, p1, o2);
            }
            if (l == 0) {
                const float mu0 = s0 * (1.f / 1024.f), mu1 = s1 * (1.f / 1024.f);
                const float rs0 = rsqrtf(p0 * (1.f / 1024.f) - mu0 * mu0 + 1e-5f);
                const float rs1 = rsqrtf(p1 * (1.f / 1024.f) - mu1 * mu1 + 1e-5f);
                RSPK[w]   = pack2(rs0, rs1);
                MURSPK[w] = pack2(mu0 * rs0, mu1 * rs1);
            }
        }
        __syncthreads();

        // ---- compute: 8 groups of 4 rows; lane = s; warp = chunk pair (r, q) ----
#pragma unroll 1
        for (int g4 = 0; g4 < 8; g4++) {
            const int go = 4 * g4;
            u64 ar0 = 0, ar1 = 0, aq0 = 0, aq1 = 0;
#pragma unroll
            for (int c = 0; c < 16; c++) {
                const ulonglong2 xr = *(const ulonglong2*)(mr0 + c * XSTR + go);
                const ulonglong2 xq = *(const ulonglong2*)(mq0 + c * XSTR + go);
                const u64 m = dup2(Mreg[c]);
                ar0 = fma2(xr.x, m, ar0); ar1 = fma2(xr.y, m, ar1);
                aq0 = fma2(xq.x, m, aq0); aq1 = fma2(xq.y, m, aq1);
            }
#pragma unroll
            for (int c = 0; c < 16; c++) {
                const ulonglong2 xr = *(const ulonglong2*)(mr1 + c * XSTR + go);
                const ulonglong2 xq = *(const ulonglong2*)(mq1 + c * XSTR + go);
                const u64 m = dup2(Mreg[c + 16]);
                ar0 = fma2(xr.x, m, ar0); ar1 = fma2(xr.y, m, ar1);
                aq0 = fma2(xq.x, m, aq0); aq1 = fma2(xq.y, m, aq1);
            }
#pragma unroll
            for (int b = 0; b < 16; b++) {
                const ulonglong2 xa = *(const ulonglong2*)(br + b * XSTR + go);
                const ulonglong2 xb = *(const ulonglong2*)(bq + b * XSTR + go);
                const u64 wr = dup2(Tr[b]);
                const u64 wq = dup2(Tq[b]);
                ar0 = fma2(xa.x, wr, ar0); ar1 = fma2(xa.y, wr, ar1);
                aq0 = fma2(xb.x, wq, aq0); aq1 = fma2(xb.y, wq, aq1);
            }
            // epilogue: out = rs*A + murs*C2 + C1 ; acc halves = {even,odd} rows
            float* orow = out + base + (size_t)go * 1024;
#pragma unroll
            for (int rp = 0; rp < 2; rp++) {
                const u64 RS2 = RSPK[2 * g4 + rp];
                const u64 MU2 = MURSPK[2 * g4 + rp];
                const u64 vr = fma2(RS2, rp ? ar1 : ar0, fma2(MU2, C2r, C1r));
                const u64 vq = fma2(RS2, rp ? aq1 : aq0, fma2(MU2, C2q, C1q));
                float a, b2;
                unpack2(a, b2, vr);
                orow[(2 * rp)     * 1024 + 32 * r + l] = a;   // coalesced 128B
                orow[(2 * rp + 1) * 1024 + 32 * r + l] = b2;
                unpack2(a, b2, vq);
                orow[(2 * rp)     * 1024 + 32 * q + l] = a;
                orow[(2 * rp + 1) * 1024 + 32 * q + l] = b2;
            }
        }
        __syncthreads();
    }
}

// ---------------------------------------------------------------------------
extern "C" void kernel_launch(void* const* d_in, const int* in_sizes, int n_in,
                              void* d_out, int out_size) {
    const float* x     = (const float*)d_in[0];
    const float* gamma = (const float*)d_in[1];
    const float* beta  = (const float*)d_in[2];
    const float* bw    = (const float*)d_in[3];
    const float* wrow  = (const float*)d_in[4];
    const float* wcol  = (const float*)d_in[5];
    const float* alpha = (const float*)d_in[6];
    const float* bias  = (const float*)d_in[7];
    float* out = (float*)d_out;

    const int rows = in_sizes[0] / 1024;
    const int ntiles = rows / 32;

    prep_kernel<<<1, 1024>>>(bw, wrow, wcol, alpha, gamma, beta, bias);

    cudaFuncSetAttribute(hbsl_kernel,
                         cudaFuncAttributeMaxDynamicSharedMemorySize, SMEM_BYTES);
    hbsl_kernel<<<148, THREADS, SMEM_BYTES>>>(x, gamma, out, ntiles);
}

// round 5
// speedup vs baseline: 1.2731x; 1.0914x over previous
#include <cuda_runtime.h>

// ---------------------------------------------------------------------------
// HierarchicalBlockShuffleLayer, single fused kernel.
//   out[32r+s] = rs*A + (mu*rs)*C2[r,s] + C1[r,s]
//   A = sum_c vg[32r+c]*M[c][s] + sum_b vg[32(31-r)+off(s)+b]*T[r][b][s]
//   vg = x*gamma; M = alpha*Wcol@Wrow^T (alpha folded); T = flip-folded BW
//   C2 = -(gamma-weighted col sums), C1 = beta-weighted col sums + bias
// Per-block constant recompute (no prep kernel). Lane = s; warp = chunk pair
// (w, 31-w). f32x2 packs row pairs. Every smem tile element read exactly once
// (block-diag FMAs reuse monarch loads via lane-half SEL).
// ---------------------------------------------------------------------------

typedef unsigned long long u64;

#define THREADS 512
#define XSTR 36

__device__ __forceinline__ u64 pack2(float a, float b) {
    u64 r; asm("mov.b64 %0, {%1, %2};" : "=l"(r) : "f"(a), "f"(b)); return r;
}
__device__ __forceinline__ u64 dup2(float a) { return pack2(a, a); }
__device__ __forceinline__ void unpack2(float& a, float& b, u64 v) {
    asm("mov.b64 {%0, %1}, %2;" : "=f"(a), "=f"(b) : "l"(v));
}
__device__ __forceinline__ u64 fma2(u64 a, u64 b, u64 c) {
    u64 d; asm("fma.rn.f32x2 %0, %1, %2, %3;" : "=l"(d) : "l"(a), "l"(b), "l"(c)); return d;
}

// Smem: XP 36864 floats | SPART 128 | RS 32 | MURS 32
#define XP_FLOATS 36864
#define SMEM_BYTES ((XP_FLOATS + 192) * 4)

__global__ void __launch_bounds__(THREADS, 1)
hbsl_kernel(const float* __restrict__ x,
            const float* __restrict__ gamma,
            const float* __restrict__ beta,
            const float* __restrict__ bw,
            const float* __restrict__ wrow,
            const float* __restrict__ wcol,
            const float* __restrict__ alphap,
            const float* __restrict__ bias,
            float* __restrict__ out,
            int ntiles) {
    extern __shared__ float XP[];
    float* SPART = XP + XP_FLOATS;      // [8 quads][2 halves][8]
    float* RS    = SPART + 128;         // [32]
    float* MURS  = RS + 32;             // [32]

    const int t = threadIdx.x;
    const int w = t >> 5, l = t & 31;
    const int r = w, q = 31 - w;
    const bool pHi = (l < 16);

    // ---- per-block constant build (once; amortized over ~7 tiles) ----
    float Mreg[32];
    {
        const float alpha = __ldg(alphap);
        float wrl[32];
#pragma unroll
        for (int k = 0; k < 32; k++) wrl[k] = __ldg(wrow + l * 32 + k);
#pragma unroll
        for (int c = 0; c < 32; c++) {
            float acc = 0.f;
#pragma unroll
            for (int k = 0; k < 32; k++) acc += __ldg(wcol + c * 32 + k) * wrl[k];
            Mreg[c] = alpha * acc;
        }
    }
    const int off = pHi ? 16 : 0;
    const int jf  = pHi ? (15 - l) : (31 - l);
    const int grpR = pHi ? (63 - 2 * r) : (62 - 2 * r);
    const int grpQ = pHi ? (63 - 2 * q) : (62 - 2 * q);
    float Tr[16], Tq[16];
#pragma unroll
    for (int b = 0; b < 16; b++) {
        Tr[b] = __ldg(bw + grpR * 256 + b * 16 + jf);
        Tq[b] = __ldg(bw + grpQ * 256 + b * 16 + jf);
    }
    u64 C1r, C2r, C1q, C2q;
    {
        float Gm = 0.f, Bm = 0.f, Gmq = 0.f, Bmq = 0.f;
#pragma unroll
        for (int c = 0; c < 32; c++) {
            Gm  += __ldg(gamma + 32 * r + c) * Mreg[c];
            Bm  += __ldg(beta  + 32 * r + c) * Mreg[c];
            Gmq += __ldg(gamma + 32 * q + c) * Mreg[c];
            Bmq += __ldg(beta  + 32 * q + c) * Mreg[c];
        }
        float Gb = 0.f, Bb = 0.f, Gbq = 0.f, Bbq = 0.f;
#pragma unroll
        for (int b = 0; b < 16; b++) {
            Gb  += __ldg(gamma + 32 * q + off + b) * Tr[b];
            Bb  += __ldg(beta  + 32 * q + off + b) * Tr[b];
            Gbq += __ldg(gamma + 32 * r + off + b) * Tq[b];
            Bbq += __ldg(beta  + 32 * r + off + b) * Tq[b];
        }
        C1r = dup2(Bm + Bb + __ldg(bias + 32 * r + l));
        C2r = dup2(-(Gm + Gb));
        C1q = dup2(Bmq + Bbq + __ldg(bias + 32 * q + l));
        C2q = dup2(-(Gmq + Gbq));
    }

    // loader role: quad a = w&7 (rows 4a..4a+3), half h = w>>3 (dims 512h..)
    const int la = w & 7, lh = w >> 3;
    const float* baseR = XP + (32 * r) * XSTR;
    const float* baseQ = XP + (32 * q) * XSTR;

    for (int tile = blockIdx.x; tile < ntiles; tile += gridDim.x) {
        const size_t base = (size_t)tile * 32768;   // 32 rows * 1024

        // ---- load: 4 rows x 512 dims per warp; STS.128 conflict-free ----
        {
            const float* xb = x + base + (size_t)(4 * la) * 1024 + lh * 512;
            const float* gb = gamma + lh * 512;
            float s0 = 0.f, s1 = 0.f, s2 = 0.f, s3 = 0.f;
            float p0 = 0.f, p1 = 0.f, p2 = 0.f, p3 = 0.f;
#pragma unroll
            for (int k = 0; k < 16; k++) {
                const int d = k * 32 + l;               // coalesced
                const float v0 = __ldg(xb + d);
                const float v1 = __ldg(xb + 1024 + d);
                const float v2 = __ldg(xb + 2048 + d);
                const float v3 = __ldg(xb + 3072 + d);
                const float g  = __ldg(gb + d);
                s0 += v0; p0 += v0 * v0;
                s1 += v1; p1 += v1 * v1;
                s2 += v2; p2 += v2 * v2;
                s3 += v3; p3 += v3 * v3;
                float4 vv = make_float4(v0 * g, v1 * g, v2 * g, v3 * g);
                *(float4*)(XP + (lh * 512 + d) * XSTR + 4 * la) = vv;
            }
#pragma unroll
            for (int o2 = 16; o2 > 0; o2 >>= 1) {
                s0 += __shfl_xor_sync(~0u, s0, o2);
                s1 += __shfl_xor_sync(~0u, s1, o2);
                s2 += __shfl_xor_sync(~0u, s2, o2);
                s3 += __shfl_xor_sync(~0u, s3, o2);
                p0 += __shfl_xor_sync(~0u, p0, o2);
                p1 += __shfl_xor_sync(~0u, p1, o2);
                p2 += __shfl_xor_sync(~0u, p2, o2);
                p3 += __shfl_xor_sync(~0u, p3, o2);
            }
            if (l == 0) {
                float* sp = SPART + (la * 2 + lh) * 8;
                sp[0] = s0; sp[1] = s1; sp[2] = s2; sp[3] = s3;
                sp[4] = p0; sp[5] = p1; sp[6] = p2; sp[7] = p3;
            }
        }
        __syncthreads();

        if (t < 32) {   // finalize stats: thread t -> row t
            const int a2 = t >> 2, jj = t & 3;
            const float s = SPART[(a2 * 2) * 8 + jj]     + SPART[(a2 * 2 + 1) * 8 + jj];
            const float p = SPART[(a2 * 2) * 8 + 4 + jj] + SPART[(a2 * 2 + 1) * 8 + 4 + jj];
            const float mu = s * (1.f / 1024.f);
            const float rs = rsqrtf(p * (1.f / 1024.f) - mu * mu + 1e-5f);
            RS[t]   = rs;
            MURS[t] = mu * rs;
        }
        __syncthreads();

        // ---- compute: 8 row-quads; per b load x(b), x(16+b) for both chunks;
        //      block-diag FMAs reuse those loads via lane-half select ----
#pragma unroll 1
        for (int a = 0; a < 8; a++) {
            const int go = 4 * a;
            u64 ar0 = 0, ar1 = 0, aq0 = 0, aq1 = 0;
#pragma unroll
            for (int b = 0; b < 16; b++) {
                const ulonglong2 xrL = *(const ulonglong2*)(baseR + b * XSTR + go);
                const ulonglong2 xrH = *(const ulonglong2*)(baseR + (16 + b) * XSTR + go);
                const ulonglong2 xqL = *(const ulonglong2*)(baseQ + b * XSTR + go);
                const ulonglong2 xqH = *(const ulonglong2*)(baseQ + (16 + b) * XSTR + go);
                const u64 mL = dup2(Mreg[b]);
                const u64 mH = dup2(Mreg[16 + b]);
                ar0 = fma2(xrL.x, mL, ar0); ar1 = fma2(xrL.y, mL, ar1);
                ar0 = fma2(xrH.x, mH, ar0); ar1 = fma2(xrH.y, mH, ar1);
                aq0 = fma2(xqL.x, mL, aq0); aq1 = fma2(xqL.y, mL, aq1);
                aq0 = fma2(xqH.x, mH, aq0); aq1 = fma2(xqH.y, mH, aq1);
                // block-diag: chunk-r outputs eat chunk-q dims (hi half for s<16)
                const u64 bx0 = pHi ? xqH.x : xqL.x;
                const u64 bx1 = pHi ? xqH.y : xqL.y;
                const u64 tr = dup2(Tr[b]);
                ar0 = fma2(bx0, tr, ar0); ar1 = fma2(bx1, tr, ar1);
                const u64 cx0 = pHi ? xrH.x : xrL.x;
                const u64 cx1 = pHi ? xrH.y : xrL.y;
                const u64 tq = dup2(Tq[b]);
                aq0 = fma2(cx0, tq, aq0); aq1 = fma2(cx1, tq, aq1);
            }
            // epilogue: out = rs*A + murs*C2 + C1
            float* orow = out + base + (size_t)go * 1024;
#pragma unroll
            for (int rp = 0; rp < 2; rp++) {
                const u64 RS2 = *(const u64*)(RS + go + 2 * rp);
                const u64 MU2 = *(const u64*)(MURS + go + 2 * rp);
                const u64 vr = fma2(RS2, rp ? ar1 : ar0, fma2(MU2, C2r, C1r));
                const u64 vq = fma2(RS2, rp ? aq1 : aq0, fma2(MU2, C2q, C1q));
                float A, B;
                unpack2(A, B, vr);
                orow[(2 * rp) * 1024 + 32 * r + l]     = A;   // coalesced 128B
                orow[(2 * rp + 1) * 1024 + 32 * r + l] = B;
                unpack2(A, B, vq);
                orow[(2 * rp) * 1024 + 32 * q + l]     = A;
                orow[(2 * rp + 1) * 1024 + 32 * q + l] = B;
            }
        }
        __syncthreads();
    }
}

// ---------------------------------------------------------------------------
extern "C" void kernel_launch(void* const* d_in, const int* in_sizes, int n_in,
                              void* d_out, int out_size) {
    const float* x     = (const float*)d_in[0];
    const float* gamma = (const float*)d_in[1];
    const float* beta  = (const float*)d_in[2];
    const float* bw    = (const float*)d_in[3];
    const float* wrow  = (const float*)d_in[4];
    const float* wcol  = (const float*)d_in[5];
    const float* alpha = (const float*)d_in[6];
    const float* bias  = (const float*)d_in[7];
    float* out = (float*)d_out;

    const int rows = in_sizes[0] / 1024;
    const int ntiles = rows / 32;

    cudaFuncSetAttribute(hbsl_kernel,
                         cudaFuncAttributeMaxDynamicSharedMemorySize, SMEM_BYTES);
    hbsl_kernel<<<148, THREADS, SMEM_BYTES>>>(x, gamma, beta, bw, wrow, wcol,
                                              alpha, bias, out, ntiles);
}

// round 7
// speedup vs baseline: 1.2866x; 1.0106x over previous
#include <cuda_runtime.h>

// ---------------------------------------------------------------------------
// HierarchicalBlockShuffleLayer, single fused kernel (R6 = R5 + layout fix).
//   out[32r+s] = rs*A + (mu*rs)*C2[r,s] + C1[r,s]
//   A = sum_c vg[32r+c]*M[c][s] + sum_b vg[32(31-r)+off(s)+b]*T[r][b][s]
// Lane = s; warp = chunk pair (w, 31-w). f32x2 packs row pairs.
// Smem tile layout: offset(D) = D*36 + 8*(D>>4)  (CUMULATIVE pad — R5's
// parity pad overlapped adjacent dims at group boundaries = write race).
// Block-diag x via per-lane-half pointer (no SELs); hi/lo group bases differ
// by 584 = 8 mod 32 banks -> divergent LDS.128 stays 1 wavefront.
// 2 barriers/tile: per-warp redundant stats finalize + SHFL broadcast.
// L2 prefetch of next tile during compute.
// ---------------------------------------------------------------------------

typedef unsigned long long u64;

#define THREADS 512
#define XSTR 36

__device__ __forceinline__ u64 pack2(float a, float b) {
    u64 r; asm("mov.b64 %0, {%1, %2};" : "=l"(r) : "f"(a), "f"(b)); return r;
}
__device__ __forceinline__ u64 dup2(float a) { return pack2(a, a); }
__device__ __forceinline__ void unpack2(float& a, float& b, u64 v) {
    asm("mov.b64 {%0, %1}, %2;" : "=f"(a), "=f"(b) : "l"(v));
}
__device__ __forceinline__ u64 fma2(u64 a, u64 b, u64 c) {
    u64 d; asm("fma.rn.f32x2 %0, %1, %2, %3;" : "=l"(d) : "l"(a), "l"(b), "l"(c)); return d;
}

// offset(D) = D*36 + 8*(D>>4); max = 1023*36 + 8*63 + 32 = 37364 -> 37376
#define XP_FLOATS 37376
#define SMEM_BYTES ((XP_FLOATS + 160) * 4)
#define CHUNK_STRIDE 1168            // offset(32r) = r * (32*36 + 8*2)
#define HI_OFF 584                   // offset(32r+16) - offset(32r) = 16*36 + 8

__global__ void __launch_bounds__(THREADS, 1)
hbsl_kernel(const float* __restrict__ x,
            const float* __restrict__ gamma,
            const float* __restrict__ beta,
            const float* __restrict__ bw,
            const float* __restrict__ wrow,
            const float* __restrict__ wcol,
            const float* __restrict__ alphap,
            const float* __restrict__ bias,
            float* __restrict__ out,
            int ntiles) {
    extern __shared__ float XP[];
    float* SPART = XP + XP_FLOATS;      // [8 quads][2 halves][8]

    const int t = threadIdx.x;
    const int w = t >> 5, l = t & 31;
    const int r = w, q = 31 - w;
    const bool pHi = (l < 16);

    // ---- per-block constant build (once; amortized over ~7 tiles) ----
    float Mreg[32];
    {
        const float alpha = __ldg(alphap);
        float wrl[32];
#pragma unroll
        for (int k = 0; k < 32; k++) wrl[k] = __ldg(wrow + l * 32 + k);
#pragma unroll
        for (int c = 0; c < 32; c++) {
            float acc = 0.f;
#pragma unroll
            for (int k = 0; k < 32; k++) acc += __ldg(wcol + c * 32 + k) * wrl[k];
            Mreg[c] = alpha * acc;
        }
    }
    const int off = pHi ? 16 : 0;
    const int jf  = pHi ? (15 - l) : (31 - l);
    const int grpR = pHi ? (63 - 2 * r) : (62 - 2 * r);
    const int grpQ = pHi ? (63 - 2 * q) : (62 - 2 * q);
    float Tr[16], Tq[16];
#pragma unroll
    for (int b = 0; b < 16; b++) {
        Tr[b] = __ldg(bw + grpR * 256 + b * 16 + jf);
        Tq[b] = __ldg(bw + grpQ * 256 + b * 16 + jf);
    }
    float C1r, C2r, C1q, C2q;
    {
        float Gm = 0.f, Bm = 0.f, Gmq = 0.f, Bmq = 0.f;
#pragma unroll
        for (int c = 0; c < 32; c++) {
            Gm  += __ldg(gamma + 32 * r + c) * Mreg[c];
            Bm  += __ldg(beta  + 32 * r + c) * Mreg[c];
            Gmq += __ldg(gamma + 32 * q + c) * Mreg[c];
            Bmq += __ldg(beta  + 32 * q + c) * Mreg[c];
        }
        float Gb = 0.f, Bb = 0.f, Gbq = 0.f, Bbq = 0.f;
#pragma unroll
        for (int b = 0; b < 16; b++) {
            Gb  += __ldg(gamma + 32 * q + off + b) * Tr[b];
            Bb  += __ldg(beta  + 32 * q + off + b) * Tr[b];
            Gbq += __ldg(gamma + 32 * r + off + b) * Tq[b];
            Bbq += __ldg(beta  + 32 * r + off + b) * Tq[b];
        }
        C1r = Bm + Bb + __ldg(bias + 32 * r + l);
        C2r = -(Gm + Gb);
        C1q = Bmq + Bbq + __ldg(bias + 32 * q + l);
        C2q = -(Gmq + Gbq);
    }

    // loader role: quad la = w&7 (rows 4la..4la+3), half lh = w>>3 (dims 512lh..)
    const int la = w & 7, lh = w >> 3;

    // compute-phase pointers (cumulative group pad)
    const float* mr0 = XP + r * CHUNK_STRIDE;
    const float* mr1 = XP + r * CHUNK_STRIDE + HI_OFF;
    const float* mq0 = XP + q * CHUNK_STRIDE;
    const float* mq1 = XP + q * CHUNK_STRIDE + HI_OFF;
    const float* bR  = pHi ? mq1 : mq0;           // block x for chunk-r outputs
    const float* bQ  = pHi ? mr1 : mr0;           // block x for chunk-q outputs

    for (int tile = blockIdx.x; tile < ntiles; tile += gridDim.x) {
        const size_t base = (size_t)tile * 32768;   // 32 rows * 1024

        // ---- load: 4 rows x 512 dims per warp; STS.128 conflict-free ----
        {
            const float* xb = x + base + (size_t)(4 * la) * 1024 + lh * 512;
            const float* gb = gamma + lh * 512;
            float s0 = 0.f, s1 = 0.f, s2 = 0.f, s3 = 0.f;
            float p0 = 0.f, p1 = 0.f, p2 = 0.f, p3 = 0.f;
#pragma unroll
            for (int k = 0; k < 16; k++) {
                const int dl = k * 32 + l;
                const int d  = lh * 512 + dl;             // global dim
                const float v0 = __ldg(xb + dl);
                const float v1 = __ldg(xb + 1024 + dl);
                const float v2 = __ldg(xb + 2048 + dl);
                const float v3 = __ldg(xb + 3072 + dl);
                const float g  = __ldg(gb + dl);
                s0 += v0; p0 += v0 * v0;
                s1 += v1; p1 += v1 * v1;
                s2 += v2; p2 += v2 * v2;
                s3 += v3; p3 += v3 * v3;
                float4 vv = make_float4(v0 * g, v1 * g, v2 * g, v3 * g);
                *(float4*)(XP + d * XSTR + (d >> 4) * 8 + 4 * la) = vv;
            }
#pragma unroll
            for (int o2 = 16; o2 > 0; o2 >>= 1) {
                s0 += __shfl_xor_sync(~0u, s0, o2);
                s1 += __shfl_xor_sync(~0u, s1, o2);
                s2 += __shfl_xor_sync(~0u, s2, o2);
                s3 += __shfl_xor_sync(~0u, s3, o2);
                p0 += __shfl_xor_sync(~0u, p0, o2);
                p1 += __shfl_xor_sync(~0u, p1, o2);
                p2 += __shfl_xor_sync(~0u, p2, o2);
                p3 += __shfl_xor_sync(~0u, p3, o2);
            }
            if (l == 0) {
                float* sp = SPART + (la * 2 + lh) * 8;
                sp[0] = s0; sp[1] = s1; sp[2] = s2; sp[3] = s3;
                sp[4] = p0; sp[5] = p1; sp[6] = p2; sp[7] = p3;
            }
        }
        __syncthreads();

        // ---- stats finalize, redundant per warp: lane l -> row l ----
        float rs_l, murs_l;
        {
            const int a2 = l >> 2, jj = l & 3;
            const float s = SPART[(a2 * 2) * 8 + jj]     + SPART[(a2 * 2 + 1) * 8 + jj];
            const float p = SPART[(a2 * 2) * 8 + 4 + jj] + SPART[(a2 * 2 + 1) * 8 + 4 + jj];
            const float mu = s * (1.f / 1024.f);
            rs_l   = rsqrtf(p * (1.f / 1024.f) - mu * mu + 1e-5f);
            murs_l = mu * rs_l;
        }

        // ---- L2 prefetch of next tile (this warp's own load region) ----
        {
            const int nt = tile + gridDim.x;
            if (nt < ntiles) {
                const char* pn = (const char*)(x + (size_t)nt * 32768 +
                                               (size_t)(4 * la) * 1024 + lh * 512);
#pragma unroll
                for (int j = 0; j < 2; j++) {
                    const int line = 2 * l + j;            // 0..63
                    const int row = line >> 4, kk = line & 15;
                    asm volatile("prefetch.global.L2 [%0];"
                                 :: "l"(pn + (size_t)row * 4096 + kk * 128));
                }
            }
        }

        // ---- compute: 8 row-quads; 6 LDS.128 + 12 fma2 per b, no SELs ----
#pragma unroll 1
        for (int a = 0; a < 8; a++) {
            const int go = 4 * a;
            u64 ar0 = 0, ar1 = 0, aq0 = 0, aq1 = 0;
#pragma unroll
            for (int b = 0; b < 16; b++) {
                const ulonglong2 xrL = *(const ulonglong2*)(mr0 + b * XSTR + go);
                const ulonglong2 xrH = *(const ulonglong2*)(mr1 + b * XSTR + go);
                const ulonglong2 xqL = *(const ulonglong2*)(mq0 + b * XSTR + go);
                const ulonglong2 xqH = *(const ulonglong2*)(mq1 + b * XSTR + go);
                const u64 mL = dup2(Mreg[b]);
                const u64 mH = dup2(Mreg[16 + b]);
                ar0 = fma2(xrL.x, mL, ar0); ar1 = fma2(xrL.y, mL, ar1);
                ar0 = fma2(xrH.x, mH, ar0); ar1 = fma2(xrH.y, mH, ar1);
                aq0 = fma2(xqL.x, mL, aq0); aq1 = fma2(xqL.y, mL, aq1);
                aq0 = fma2(xqH.x, mH, aq0); aq1 = fma2(xqH.y, mH, aq1);
                const ulonglong2 bx = *(const ulonglong2*)(bR + b * XSTR + go);
                const ulonglong2 cx = *(const ulonglong2*)(bQ + b * XSTR + go);
                const u64 tr = dup2(Tr[b]);
                const u64 tq = dup2(Tq[b]);
                ar0 = fma2(bx.x, tr, ar0); ar1 = fma2(bx.y, tr, ar1);
                aq0 = fma2(cx.x, tq, aq0); aq1 = fma2(cx.y, tq, aq1);
            }
            // epilogue: out = rs*A + murs*C2 + C1 ; rs via SHFL broadcast
            float* orow = out + base + (size_t)go * 1024;
#pragma unroll
            for (int rp = 0; rp < 2; rp++) {
                const int e = go + 2 * rp;
                const u64 RS2 = pack2(__shfl_sync(~0u, rs_l, e),
                                      __shfl_sync(~0u, rs_l, e + 1));
                const u64 MU2 = pack2(__shfl_sync(~0u, murs_l, e),
                                      __shfl_sync(~0u, murs_l, e + 1));
                const u64 vr = fma2(RS2, rp ? ar1 : ar0, fma2(MU2, dup2(C2r), dup2(C1r)));
                const u64 vq = fma2(RS2, rp ? aq1 : aq0, fma2(MU2, dup2(C2q), dup2(C1q)));
                float A, B;
                unpack2(A, B, vr);
                orow[(2 * rp) * 1024 + 32 * r + l]     = A;   // coalesced 128B
                orow[(2 * rp + 1) * 1024 + 32 * r + l] = B;
                unpack2(A, B, vq);
                orow[(2 * rp) * 1024 + 32 * q + l]     = A;
                orow[(2 * rp + 1) * 1024 + 32 * q + l] = B;
            }
        }
        __syncthreads();
    }
}

// ---------------------------------------------------------------------------
extern "C" void kernel_launch(void* const* d_in, const int* in_sizes, int n_in,
                              void* d_out, int out_size) {
    const float* x     = (const float*)d_in[0];
    const float* gamma = (const float*)d_in[1];
    const float* beta  = (const float*)d_in[2];
    const float* bw    = (const float*)d_in[3];
    const float* wrow  = (const float*)d_in[4];
    const float* wcol  = (const float*)d_in[5];
    const float* alpha = (const float*)d_in[6];
    const float* bias  = (const float*)d_in[7];
    float* out = (float*)d_out;

    const int rows = in_sizes[0] / 1024;
    const int ntiles = rows / 32;

    cudaFuncSetAttribute(hbsl_kernel,
                         cudaFuncAttributeMaxDynamicSharedMemorySize, SMEM_BYTES);
    hbsl_kernel<<<148, THREADS, SMEM_BYTES>>>(x, gamma, beta, bw, wrow, wcol,
                                              alpha, bias, out, ntiles);
}